// round 1
// baseline (speedup 1.0000x reference)
#include <cuda_runtime.h>
#include <cstdint>
#include <cstddef>

#define NB 4096
#define NS 544
#define NH 256
#define ND 128
#define NM 50000
#define NK 50
#define BT 32        // batch rows per CTA in dnd kernel
#define MC 64        // keys per chunk
#define NCH ((NM + MC - 1) / MC)

// ---------------- scratch (static device globals; no allocations) ----------
__device__ float g_h[NB * NH];
__device__ float g_qpre[NB * ND];
__device__ float g_q[NB * ND];
__device__ float g_q2[NB];
__device__ float g_k2[NM];
__device__ float g_v1[NB * NH];
__device__ float g_v2[NB * ND];
__device__ float g_net[NB];

// ---------------- helpers ----------------
__device__ __forceinline__ void cp16(uint32_t dst, const void* src) {
    asm volatile("cp.async.ca.shared.global [%0], [%1], 16;\n" :: "r"(dst), "l"(src));
}
__device__ __forceinline__ float warp_allred(float v) {
#pragma unroll
    for (int o = 16; o; o >>= 1) v += __shfl_xor_sync(0xffffffffu, v, o);
    return v;
}

// ---------------- k2[m] = ||key_m||^2 (warp per key) ----------------
__global__ void k2_kernel(const float* __restrict__ keys, float* __restrict__ k2) {
    int w = (blockIdx.x * blockDim.x + threadIdx.x) >> 5;
    int lane = threadIdx.x & 31;
    float4 v = *(const float4*)(keys + (size_t)w * ND + lane * 4);
    float s = v.x * v.x + v.y * v.y + v.z * v.z + v.w * v.w;
    s = warp_allred(s);
    if (lane == 0) k2[w] = s;
}

// ---------------- tiled SGEMM: C = op(A[M,K] @ W[K,N] + bias) --------------
template <int RELU>
__global__ void gemm_kernel(const float* __restrict__ A, const float* __restrict__ W,
                            const float* __restrict__ bias, float* __restrict__ C,
                            int Md, int Nd, int Kd) {
    __shared__ float As[64][17];
    __shared__ float Bs[16][64];
    const int tid = threadIdx.x;
    const int tn = tid & 15, tm = tid >> 4;
    const int row0 = blockIdx.y << 6, col0 = blockIdx.x << 6;
    const int arow = tid >> 2, acol = (tid & 3) << 2;
    const int brow = tid >> 4, bcol = (tid & 15) << 2;
    float acc[4][4] = {};
    for (int k0 = 0; k0 < Kd; k0 += 16) {
        float4 av = *(const float4*)(A + (size_t)(row0 + arow) * Kd + k0 + acol);
        float4 bv = *(const float4*)(W + (size_t)(k0 + brow) * Nd + col0 + bcol);
        As[arow][acol + 0] = av.x; As[arow][acol + 1] = av.y;
        As[arow][acol + 2] = av.z; As[arow][acol + 3] = av.w;
        *(float4*)&Bs[brow][bcol] = bv;
        __syncthreads();
#pragma unroll
        for (int kk = 0; kk < 16; ++kk) {
            float aa[4];
#pragma unroll
            for (int i = 0; i < 4; ++i) aa[i] = As[tm * 4 + i][kk];
            float4 b4 = *(float4*)&Bs[kk][tn * 4];
            float bb[4] = {b4.x, b4.y, b4.z, b4.w};
#pragma unroll
            for (int i = 0; i < 4; ++i)
#pragma unroll
                for (int j = 0; j < 4; ++j)
                    acc[i][j] = fmaf(aa[i], bb[j], acc[i][j]);
        }
        __syncthreads();
    }
    float4 bz = *(const float4*)(bias + col0 + tn * 4);
    float bb[4] = {bz.x, bz.y, bz.z, bz.w};
#pragma unroll
    for (int i = 0; i < 4; ++i) {
        float v0 = acc[i][0] + bb[0], v1 = acc[i][1] + bb[1];
        float v2 = acc[i][2] + bb[2], v3 = acc[i][3] + bb[3];
        if (RELU) {
            v0 = fmaxf(v0, 0.f); v1 = fmaxf(v1, 0.f);
            v2 = fmaxf(v2, 0.f); v3 = fmaxf(v3, 0.f);
        }
        float4 o; o.x = v0; o.y = v1; o.z = v2; o.w = v3;
        *(float4*)(C + (size_t)(row0 + tm * 4 + i) * Nd + col0 + tn * 4) = o;
    }
}

// ---------------- LayerNorm + q2 (warp per row, D=128) ----------------
__global__ void ln_kernel(const float* __restrict__ x, const float* __restrict__ g,
                          const float* __restrict__ b, float* __restrict__ q,
                          float* __restrict__ q2) {
    int row = (blockIdx.x * blockDim.x + threadIdx.x) >> 5;
    int lane = threadIdx.x & 31;
    float4 v = *(const float4*)(x + (size_t)row * ND + lane * 4);
    float mu = warp_allred(v.x + v.y + v.z + v.w) * (1.f / 128.f);
    float d0 = v.x - mu, d1 = v.y - mu, d2 = v.z - mu, d3 = v.w - mu;
    float var = warp_allred(d0 * d0 + d1 * d1 + d2 * d2 + d3 * d3) * (1.f / 128.f);
    float inv = rsqrtf(var + 1e-5f);
    float4 gg = *(const float4*)(g + lane * 4);
    float4 bb = *(const float4*)(b + lane * 4);
    float4 o;
    o.x = d0 * inv * gg.x + bb.x;
    o.y = d1 * inv * gg.y + bb.y;
    o.z = d2 * inv * gg.z + bb.z;
    o.w = d3 * inv * gg.w + bb.w;
    *(float4*)(q + (size_t)row * ND + lane * 4) = o;
    float qq = warp_allred(o.x * o.x + o.y * o.y + o.z * o.z + o.w * o.w);
    if (lane == 0) q2[row] = qq;
}

// ---------------- net[b] = v2[b] . V3 + c3 (warp per row) ----------------
__global__ void net_kernel(const float* __restrict__ v2, const float* __restrict__ V3,
                           const float* __restrict__ c3, float* __restrict__ net) {
    int row = (blockIdx.x * blockDim.x + threadIdx.x) >> 5;
    int lane = threadIdx.x & 31;
    float4 a = *(const float4*)(v2 + (size_t)row * ND + lane * 4);
    float4 w = *(const float4*)(V3 + lane * 4);
    float s = warp_allred(a.x * w.x + a.y * w.y + a.z * w.z + a.w * w.w);
    if (lane == 0) net[row] = s + c3[0];
}

// ---------------- fused distance GEMM + streaming top-50 ----------------
// smem layout (floats):
#define SM_KS   0                       // 2 * 64 * 128 = 16384 (xor-swizzled key tiles)
#define SM_QS   16384                   // 32 * 132 = 4224   (padded q tile)
#define SM_K2   (SM_QS + 4224)          // 2 * 64
#define SM_Q2   (SM_K2 + 128)           // 32
#define SM_THR  (SM_Q2 + 32)            // 32
#define SM_CD   (SM_THR + 32)           // 32 * 64 = 2048 (candidate dists)
#define SM_HD   (SM_CD + 2048)          // 32 * 50 = 1600 (heap dists)
#define SM_CI   (SM_HD + 1600)          // 32 * 64 ints
#define SM_HI   (SM_CI + 2048)          // 32 * 50 ints
#define SM_CNT  (SM_HI + 1600)          // 32 ints
#define SM_TOT  (SM_CNT + 32)
#define SMEM_BYTES (SM_TOT * 4)         // 112512 bytes

__device__ __forceinline__ void dnd_load_chunk(int ch, int tid, uint32_t ks_s, uint32_t k2_s,
                                               const float* __restrict__ keys,
                                               const float* __restrict__ k2g) {
    const int buf = ch & 1;
    const int m0 = ch * MC;
    const uint32_t kd = ks_s + buf * (MC * ND * 4);
#pragma unroll
    for (int it = 0; it < 8; ++it) {
        int idx = tid + (it << 8);
        int m = idx >> 5, dc = idx & 31;
        int gm = m0 + m;
        if (gm < NM)
            cp16(kd + m * 512 + ((dc ^ ((m >> 2) & 7)) << 4),
                 keys + (size_t)gm * ND + (dc << 2));
    }
    if (tid < 16) {
        int mm = tid << 2;
        if (m0 + mm < NM) cp16(k2_s + (buf << 8) + (tid << 4), k2g + m0 + mm);
    }
    asm volatile("cp.async.commit_group;\n" ::: "memory");
}

__global__ void __launch_bounds__(256, 1)
dnd_kernel(const float* __restrict__ q, const float* __restrict__ q2g,
           const float* __restrict__ k2g, const float* __restrict__ keys,
           const float* __restrict__ vals, const float* __restrict__ net,
           float* __restrict__ out) {
    extern __shared__ float sm[];
    float* ks  = sm + SM_KS;
    float* qs  = sm + SM_QS;
    float* k2s = sm + SM_K2;
    float* q2s = sm + SM_Q2;
    float* thr = sm + SM_THR;
    float* cd  = sm + SM_CD;
    float* hd  = sm + SM_HD;
    int* ci  = (int*)(sm + SM_CI);
    int* hi  = (int*)(sm + SM_HI);
    int* cnt = (int*)(sm + SM_CNT);

    const int tid = threadIdx.x;
    const int b0 = blockIdx.x * BT;
    const uint32_t ks_s = (uint32_t)__cvta_generic_to_shared(ks);
    const uint32_t k2_s = (uint32_t)__cvta_generic_to_shared(k2s);
    const float INF = __int_as_float(0x7f800000);

    dnd_load_chunk(0, tid, ks_s, k2_s, keys, k2g);

    // init q tile / q2 / thresholds / heaps
    for (int i = tid; i < BT * ND; i += 256) {
        int r = i >> 7, d = i & 127;
        qs[r * 132 + d] = q[(size_t)(b0 + r) * ND + d];
    }
    if (tid < BT) {
        q2s[tid] = q2g[b0 + tid];
        thr[tid] = INF;
        cnt[tid] = 0;
    }
    for (int i = tid; i < BT * NK; i += 256) { hd[i] = INF; hi[i] = 0; }

    const int tm = tid >> 4, tc = tid & 15;
    const int r0 = tm << 1, c0 = tc << 2;
    const int sw = tc & 7;
    const float* kb0 = ks + c0 * ND;

    for (int ch = 0; ch < NCH; ++ch) {
        const int buf = ch & 1;
        if (ch + 1 < NCH) {
            dnd_load_chunk(ch + 1, tid, ks_s, k2_s, keys, k2g);
            asm volatile("cp.async.wait_group 1;\n" ::: "memory");
        } else {
            asm volatile("cp.async.wait_group 0;\n" ::: "memory");
        }
        __syncthreads();

        const float* kb = kb0 + buf * (MC * ND);
        float acc[2][4] = {};
#pragma unroll 4
        for (int dc = 0; dc < 32; ++dc) {
            const int off = (dc ^ sw) << 2;
            float4 q0 = *(const float4*)(qs + r0 * 132 + (dc << 2));
            float4 q1 = *(const float4*)(qs + (r0 + 1) * 132 + (dc << 2));
            float4 k0 = *(const float4*)(kb + off);
            float4 k1 = *(const float4*)(kb + ND + off);
            float4 k2v = *(const float4*)(kb + 2 * ND + off);
            float4 k3 = *(const float4*)(kb + 3 * ND + off);
            float qa[2][4] = {{q0.x, q0.y, q0.z, q0.w}, {q1.x, q1.y, q1.z, q1.w}};
            float ka[4][4] = {{k0.x, k0.y, k0.z, k0.w}, {k1.x, k1.y, k1.z, k1.w},
                              {k2v.x, k2v.y, k2v.z, k2v.w}, {k3.x, k3.y, k3.z, k3.w}};
#pragma unroll
            for (int i = 0; i < 2; ++i)
#pragma unroll
                for (int j = 0; j < 4; ++j)
#pragma unroll
                    for (int t = 0; t < 4; ++t)
                        acc[i][j] = fmaf(qa[i][t], ka[j][t], acc[i][j]);
        }

        // threshold filter -> candidate buffer
        const int m0 = ch * MC;
#pragma unroll
        for (int i = 0; i < 2; ++i) {
            const int r = r0 + i;
            const float t = thr[r];
            const float qq = q2s[r];
#pragma unroll
            for (int j = 0; j < 4; ++j) {
                int gm = m0 + c0 + j;
                float dist = qq + k2s[buf * 64 + c0 + j] - 2.f * acc[i][j];
                if (gm < NM && dist < t) {
                    int p = atomicAdd(&cnt[r], 1);
                    cd[r * 64 + p] = dist;
                    ci[r * 64 + p] = gm;
                }
            }
        }
        __syncthreads();

        // flush candidates into per-row 50-element max-heap (thread r owns row r)
        if (tid < BT) {
            const int r = tid;
            int c = cnt[r];
            if (c > 0) {
                float* hdR = hd + r * NK;
                int* hiR = hi + r * NK;
                for (int j = 0; j < c; ++j) {
                    float dv = cd[r * 64 + j];
                    if (dv < hdR[0]) {
                        int iv = ci[r * 64 + j];
                        int p = 0;
                        while (true) {
                            int l = 2 * p + 1;
                            if (l >= NK) break;
                            int rr = l + 1;
                            int big = (rr < NK && hdR[rr] > hdR[l]) ? rr : l;
                            if (hdR[big] > dv) {
                                hdR[p] = hdR[big]; hiR[p] = hiR[big]; p = big;
                            } else break;
                        }
                        hdR[p] = dv; hiR[p] = iv;
                    }
                }
                thr[r] = hdR[0];
                cnt[r] = 0;
            }
        }
        __syncthreads();
    }

    // epilogue: weighted average over the 50 nearest + blend with net value
    const int w = tid >> 5, lane = tid & 31;
#pragma unroll
    for (int rr = 0; rr < 4; ++rr) {
        const int r = w * 4 + rr;
        float wsum = 0.f, vsum = 0.f;
        for (int j = lane; j < NK; j += 32) {
            float dd = hd[r * NK + j];
            float wt = 1.f / (dd + 1e-7f);
            wsum += wt;
            vsum += wt * vals[hi[r * NK + j]];
        }
        wsum = warp_allred(wsum);
        vsum = warp_allred(vsum);
        if (lane == 0)
            out[b0 + r] = 0.9f * (vsum / wsum) + 0.1f * net[b0 + r];
    }
}

// ---------------- launch ----------------
extern "C" void kernel_launch(void* const* d_in, const int* in_sizes, int n_in,
                              void* d_out, int out_size) {
    const float* states     = (const float*)d_in[0];
    const float* W1         = (const float*)d_in[1];
    const float* b1         = (const float*)d_in[2];
    const float* W2         = (const float*)d_in[3];
    const float* b2         = (const float*)d_in[4];
    const float* ln_g       = (const float*)d_in[5];
    const float* ln_b       = (const float*)d_in[6];
    const float* mem_keys   = (const float*)d_in[7];
    const float* mem_values = (const float*)d_in[8];
    const float* V1         = (const float*)d_in[9];
    const float* c1         = (const float*)d_in[10];
    const float* V2         = (const float*)d_in[11];
    const float* c2         = (const float*)d_in[12];
    const float* V3         = (const float*)d_in[13];
    const float* c3         = (const float*)d_in[14];
    float* out = (float*)d_out;

    void *ph, *pqpre, *pq, *pq2, *pk2, *pv1, *pv2, *pnet;
    cudaGetSymbolAddress(&ph, g_h);
    cudaGetSymbolAddress(&pqpre, g_qpre);
    cudaGetSymbolAddress(&pq, g_q);
    cudaGetSymbolAddress(&pq2, g_q2);
    cudaGetSymbolAddress(&pk2, g_k2);
    cudaGetSymbolAddress(&pv1, g_v1);
    cudaGetSymbolAddress(&pv2, g_v2);
    cudaGetSymbolAddress(&pnet, g_net);

    cudaFuncSetAttribute(dnd_kernel, cudaFuncAttributeMaxDynamicSharedMemorySize, SMEM_BYTES);

    k2_kernel<<<NM / 8, 256>>>(mem_keys, (float*)pk2);

    gemm_kernel<1><<<dim3(NH / 64, NB / 64), 256>>>(states, W1, b1, (float*)ph, NB, NH, NS);
    gemm_kernel<1><<<dim3(NH / 64, NB / 64), 256>>>(states, V1, c1, (float*)pv1, NB, NH, NS);
    gemm_kernel<0><<<dim3(ND / 64, NB / 64), 256>>>((const float*)ph, W2, b2, (float*)pqpre, NB, ND, NH);
    gemm_kernel<1><<<dim3(ND / 64, NB / 64), 256>>>((const float*)pv1, V2, c2, (float*)pv2, NB, ND, NH);

    ln_kernel<<<NB / 8, 256>>>((const float*)pqpre, ln_g, ln_b, (float*)pq, (float*)pq2);
    net_kernel<<<NB / 8, 256>>>((const float*)pv2, V3, c3, (float*)pnet);

    dnd_kernel<<<NB / BT, 256, SMEM_BYTES>>>((const float*)pq, (const float*)pq2,
                                             (const float*)pk2, mem_keys, mem_values,
                                             (const float*)pnet, out);
}

// round 4
// speedup vs baseline: 1.8334x; 1.8334x over previous
#include <cuda_runtime.h>
#include <cuda_bf16.h>
#include <cstdint>
#include <cstddef>

#define NB 4096
#define NS 544
#define NH 256
#define ND 128
#define NM 50000
#define NK 50
#define K2N 64           // candidates kept per split
#define NSPLIT 4
#define SPLEN 12544      // 98 * 128
#define TILEN 128
#define F_INF __int_as_float(0x7f800000)

// ---------------- scratch (static device globals; no allocations) ----------
__device__ float g_h[NB * NH];
__device__ float g_qpre[NB * ND];
__device__ float g_q[NB * ND];
__device__ float g_q2[NB];
__device__ float g_k2[NM];
__device__ float g_v1[NB * NH];
__device__ float g_v2[NB * ND];
__device__ float g_net[NB];
__device__ __nv_bfloat16 g_keys16[NM * ND];
__device__ int g_cand[NB * (NSPLIT * K2N)];

// ---------------- helpers ----------------
__device__ __forceinline__ uint32_t smem_u32(const void* p) {
    uint32_t a;
    asm("{ .reg .u64 t; cvta.to.shared.u64 t, %1; cvt.u32.u64 %0, t; }" : "=r"(a) : "l"(p));
    return a;
}
__device__ __forceinline__ void cp16(uint32_t dst, const void* src) {
    asm volatile("cp.async.ca.shared.global [%0], [%1], 16;\n" :: "r"(dst), "l"(src));
}
__device__ __forceinline__ float warp_allred(float v) {
#pragma unroll
    for (int o = 16; o; o >>= 1) v += __shfl_xor_sync(0xffffffffu, v, o);
    return v;
}
__device__ __forceinline__ void ldsm_x4(uint32_t& r0, uint32_t& r1, uint32_t& r2,
                                        uint32_t& r3, uint32_t addr) {
    asm volatile("ldmatrix.sync.aligned.m8n8.x4.shared.b16 {%0,%1,%2,%3}, [%4];"
                 : "=r"(r0), "=r"(r1), "=r"(r2), "=r"(r3) : "r"(addr));
}
__device__ __forceinline__ void mma_bf16(float* c, const uint32_t* a, uint32_t b0, uint32_t b1) {
    asm volatile("mma.sync.aligned.m16n8k16.row.col.f32.bf16.bf16.f32 "
                 "{%0,%1,%2,%3}, {%4,%5,%6,%7}, {%8,%9}, {%0,%1,%2,%3};"
                 : "+f"(c[0]), "+f"(c[1]), "+f"(c[2]), "+f"(c[3])
                 : "r"(a[0]), "r"(a[1]), "r"(a[2]), "r"(a[3]), "r"(b0), "r"(b1));
}

// ---------------- k2 / key conversion ----------------
__global__ void k2_kernel(const float* __restrict__ keys, float* __restrict__ k2) {
    int w = (blockIdx.x * blockDim.x + threadIdx.x) >> 5;
    int lane = threadIdx.x & 31;
    float4 v = *(const float4*)(keys + (size_t)w * ND + lane * 4);
    float s = v.x * v.x + v.y * v.y + v.z * v.z + v.w * v.w;
    s = warp_allred(s);
    if (lane == 0) k2[w] = s;
}

__global__ void cvt_keys_kernel(const float* __restrict__ keys, __nv_bfloat16* __restrict__ out) {
    int i = blockIdx.x * blockDim.x + threadIdx.x;
    float4 v = *(const float4*)(keys + (size_t)i * 4);
    __nv_bfloat162 a = __floats2bfloat162_rn(v.x, v.y);
    __nv_bfloat162 b = __floats2bfloat162_rn(v.z, v.w);
    uint2 o;
    o.x = *(uint32_t*)&a;
    o.y = *(uint32_t*)&b;
    *(uint2*)(out + (size_t)i * 4) = o;
}

// ---------------- encoder GEMMs (SIMT, small) ----------------
template <int RELU>
__global__ void gemm_kernel(const float* __restrict__ A, const float* __restrict__ W,
                            const float* __restrict__ bias, float* __restrict__ C,
                            int Md, int Nd, int Kd) {
    __shared__ float As[64][17];
    __shared__ float Bs[16][64];
    const int tid = threadIdx.x;
    const int tn = tid & 15, tm = tid >> 4;
    const int row0 = blockIdx.y << 6, col0 = blockIdx.x << 6;
    const int arow = tid >> 2, acol = (tid & 3) << 2;
    const int brow = tid >> 4, bcol = (tid & 15) << 2;
    float acc[4][4] = {};
    for (int k0 = 0; k0 < Kd; k0 += 16) {
        float4 av = *(const float4*)(A + (size_t)(row0 + arow) * Kd + k0 + acol);
        float4 bv = *(const float4*)(W + (size_t)(k0 + brow) * Nd + col0 + bcol);
        As[arow][acol + 0] = av.x; As[arow][acol + 1] = av.y;
        As[arow][acol + 2] = av.z; As[arow][acol + 3] = av.w;
        *(float4*)&Bs[brow][bcol] = bv;
        __syncthreads();
#pragma unroll
        for (int kk = 0; kk < 16; ++kk) {
            float aa[4];
#pragma unroll
            for (int i = 0; i < 4; ++i) aa[i] = As[tm * 4 + i][kk];
            float4 b4 = *(float4*)&Bs[kk][tn * 4];
            float bb[4] = {b4.x, b4.y, b4.z, b4.w};
#pragma unroll
            for (int i = 0; i < 4; ++i)
#pragma unroll
                for (int j = 0; j < 4; ++j)
                    acc[i][j] = fmaf(aa[i], bb[j], acc[i][j]);
        }
        __syncthreads();
    }
    float4 bz = *(const float4*)(bias + col0 + tn * 4);
    float bb[4] = {bz.x, bz.y, bz.z, bz.w};
#pragma unroll
    for (int i = 0; i < 4; ++i) {
        float v0 = acc[i][0] + bb[0], v1 = acc[i][1] + bb[1];
        float v2 = acc[i][2] + bb[2], v3 = acc[i][3] + bb[3];
        if (RELU) {
            v0 = fmaxf(v0, 0.f); v1 = fmaxf(v1, 0.f);
            v2 = fmaxf(v2, 0.f); v3 = fmaxf(v3, 0.f);
        }
        float4 o; o.x = v0; o.y = v1; o.z = v2; o.w = v3;
        *(float4*)(C + (size_t)(row0 + tm * 4 + i) * Nd + col0 + tn * 4) = o;
    }
}

__global__ void ln_kernel(const float* __restrict__ x, const float* __restrict__ g,
                          const float* __restrict__ b, float* __restrict__ q,
                          float* __restrict__ q2) {
    int row = (blockIdx.x * blockDim.x + threadIdx.x) >> 5;
    int lane = threadIdx.x & 31;
    float4 v = *(const float4*)(x + (size_t)row * ND + lane * 4);
    float mu = warp_allred(v.x + v.y + v.z + v.w) * (1.f / 128.f);
    float d0 = v.x - mu, d1 = v.y - mu, d2 = v.z - mu, d3 = v.w - mu;
    float var = warp_allred(d0 * d0 + d1 * d1 + d2 * d2 + d3 * d3) * (1.f / 128.f);
    float inv = rsqrtf(var + 1e-5f);
    float4 gg = *(const float4*)(g + lane * 4);
    float4 bb = *(const float4*)(b + lane * 4);
    float4 o;
    o.x = d0 * inv * gg.x + bb.x;
    o.y = d1 * inv * gg.y + bb.y;
    o.z = d2 * inv * gg.z + bb.z;
    o.w = d3 * inv * gg.w + bb.w;
    *(float4*)(q + (size_t)row * ND + lane * 4) = o;
    float qq = warp_allred(o.x * o.x + o.y * o.y + o.z * o.z + o.w * o.w);
    if (lane == 0) q2[row] = qq;
}

__global__ void net_kernel(const float* __restrict__ v2, const float* __restrict__ V3,
                           const float* __restrict__ c3, float* __restrict__ net) {
    int row = (blockIdx.x * blockDim.x + threadIdx.x) >> 5;
    int lane = threadIdx.x & 31;
    float4 a = *(const float4*)(v2 + (size_t)row * ND + lane * 4);
    float4 w = *(const float4*)(V3 + lane * 4);
    float s = warp_allred(a.x * w.x + a.y * w.y + a.z * w.z + a.w * w.w);
    if (lane == 0) net[row] = s + c3[0];
}

// ---------------- phase 1: mma.sync bf16 GEMM + streaming top-64 ----------------
// smem byte offsets:
#define SM_B    0                 // 2 x 32768: key tiles, swizzled (row*256 + (u^(row&7))*16)
#define SM_DIST 65536             // 128 x 132 floats = 67584  (also q bf16 staging at start)
#define SM_HD   133120            // 128 x 65 floats (heap dists, stride 65)
#define SM_HI   166400            // 128 x 65 ints
#define SM_K2   199680            // 2 x 128 floats
#define SM_TOT  200704

__device__ __forceinline__ void heap_push(float* H, int* I, float sc, int gm) {
    int p = 0;
    while (true) {
        int l = 2 * p + 1;
        if (l >= K2N) break;
        int rc = l + 1;
        float dl = H[l];
        float dr = (rc < K2N) ? H[rc] : -1e30f;
        int big; float db;
        if (dr > dl) { big = rc; db = dr; } else { big = l; db = dl; }
        if (db > sc) { H[p] = db; I[p] = I[big]; p = big; } else break;
    }
    H[p] = sc; I[p] = gm;
}

__device__ __forceinline__ void p1_load_tile(int t, int m0s, int tid, uint32_t sb,
                                             float* k2s, const __nv_bfloat16* keys16,
                                             const float* k2g) {
    const int buf = t & 1;
    const int m0t = m0s + t * TILEN;
#pragma unroll
    for (int it = 0; it < 8; ++it) {
        int idx = tid + (it << 8);
        int row = idx >> 4, u = idx & 15;
        int gm = m0t + row;
        if (gm < NM)
            cp16(sb + SM_B + buf * 32768 + row * 256 + ((u ^ (row & 7)) << 4),
                 keys16 + (size_t)gm * ND + u * 8);
    }
    if (tid < 32) {
        int g0 = m0t + tid * 4;
        if (g0 + 3 < NM) {
            cp16(sb + SM_K2 + buf * 512 + (tid << 4), k2g + g0);
        } else {
#pragma unroll
            for (int u2 = 0; u2 < 4; ++u2) {
                int g = g0 + u2;
                k2s[buf * 128 + tid * 4 + u2] = (g < NM) ? __ldg(k2g + g) : F_INF;
            }
        }
    }
    asm volatile("cp.async.commit_group;\n" ::: "memory");
}

__global__ void __launch_bounds__(256, 1)
p1_kernel(const float* __restrict__ q, const __nv_bfloat16* __restrict__ keys16,
          const float* __restrict__ k2g, int* __restrict__ cand) {
    extern __shared__ __align__(16) char sm[];
    const uint32_t sb = smem_u32(sm);
    float* dist = (float*)(sm + SM_DIST);
    float* hd = (float*)(sm + SM_HD);
    int* hi = (int*)(sm + SM_HI);
    float* k2s = (float*)(sm + SM_K2);

    const int tid = threadIdx.x;
    const int w = tid >> 5;
    const int lt = tid & 31;
    const int s = blockIdx.x, qb = blockIdx.y;
    const int m0s = s * SPLEN;
    const int mlen = min(SPLEN, NM - m0s);
    const int T = (mlen + TILEN - 1) / TILEN;

    // init heaps (128 rows x 64, stride 65)
    for (int i = tid; i < 128 * K2N; i += 256) {
        int r = i >> 6, j = i & 63;
        hd[r * 65 + j] = F_INF;
        hi[r * 65 + j] = m0s;
    }

    // stage q block as bf16 (swizzled) into the DIST region
#pragma unroll
    for (int it = 0; it < 8; ++it) {
        int idx = tid + (it << 8);
        int row = idx >> 4, u = idx & 15;
        const float* src = q + (size_t)(qb * 128 + row) * ND + u * 8;
        float4 v0 = *(const float4*)src;
        float4 v1 = *(const float4*)(src + 4);
        __nv_bfloat162 p0 = __floats2bfloat162_rn(v0.x, v0.y);
        __nv_bfloat162 p1 = __floats2bfloat162_rn(v0.z, v0.w);
        __nv_bfloat162 p2 = __floats2bfloat162_rn(v1.x, v1.y);
        __nv_bfloat162 p3 = __floats2bfloat162_rn(v1.z, v1.w);
        uint4 pk;
        pk.x = *(uint32_t*)&p0; pk.y = *(uint32_t*)&p1;
        pk.z = *(uint32_t*)&p2; pk.w = *(uint32_t*)&p3;
        *(uint4*)(sm + SM_DIST + row * 256 + ((u ^ (row & 7)) << 4)) = pk;
    }
    __syncthreads();

    // load persistent A fragments (warp w owns q rows [w*16, w*16+16))
    uint32_t af[8][4];
    {
        int mrow = w * 16 + (lt & 7) + ((lt >> 3) & 1) * 8;
        int kh = lt >> 4;
        uint32_t abase = sb + SM_DIST + mrow * 256;
        int msw = mrow & 7;
#pragma unroll
        for (int kk = 0; kk < 8; ++kk)
            ldsm_x4(af[kk][0], af[kk][1], af[kk][2], af[kk][3],
                    abase + ((((kk << 1) | kh) ^ msw) << 4));
    }
    __syncthreads();   // staging region now free -> dist buffer

    p1_load_tile(0, m0s, tid, sb, k2s, keys16, k2g);

    float thr = F_INF;
    float* H = hd + tid * 65;
    int* I = hi + tid * 65;
    const int nbase = (lt >> 4) * 8 + (lt & 7);   // n within tile-pair for ldmatrix B
    const int hh = (lt >> 3) & 1;
    const int r0 = w * 16 + (lt >> 2);
    const int cbase = (lt & 3) << 1;

    for (int t = 0; t < T; ++t) {
        const int buf = t & 1;
        asm volatile("cp.async.wait_group 0;\n" ::: "memory");
        __syncthreads();
        if (t + 1 < T) p1_load_tile(t + 1, m0s, tid, sb, k2s, keys16, k2g);

        // MMA: 128 q rows x 128 keys x 128 dims
        float acc[16][4];
#pragma unroll
        for (int j = 0; j < 16; ++j)
#pragma unroll
            for (int e = 0; e < 4; ++e) acc[j][e] = 0.f;

        const uint32_t bbase = sb + SM_B + buf * 32768;
#pragma unroll
        for (int kk = 0; kk < 8; ++kk) {
#pragma unroll
            for (int jp = 0; jp < 8; ++jp) {
                int n = jp * 16 + nbase;
                uint32_t addr = bbase + n * 256 + ((((kk << 1) | hh) ^ (n & 7)) << 4);
                uint32_t b0, b1, b2, b3;
                ldsm_x4(b0, b1, b2, b3, addr);
                mma_bf16(acc[2 * jp], af[kk], b0, b1);
                mma_bf16(acc[2 * jp + 1], af[kk], b2, b3);
            }
        }

        // write scores (k2 - 2*dot) to dist[128][132]
#pragma unroll
        for (int j = 0; j < 16; ++j) {
            int c = j * 8 + cbase;
            float2 kk2 = *(float2*)(k2s + buf * 128 + c);
            float2 s0, s1;
            s0.x = fmaf(acc[j][0], -2.f, kk2.x);
            s0.y = fmaf(acc[j][1], -2.f, kk2.y);
            s1.x = fmaf(acc[j][2], -2.f, kk2.x);
            s1.y = fmaf(acc[j][3], -2.f, kk2.y);
            *(float2*)(dist + r0 * 132 + c) = s0;
            *(float2*)(dist + (r0 + 8) * 132 + c) = s1;
        }
        __syncthreads();

        // per-row scan + heap maintenance (thread tid owns q row tid)
        if (tid < 128) {
            const int m0t = m0s + t * TILEN;
            const float* drow = dist + tid * 132;
#pragma unroll 8
            for (int c4 = 0; c4 < 32; ++c4) {
                float4 v = *(const float4*)(drow + c4 * 4);
                int cb = m0t + c4 * 4;
                if (v.x < thr) { heap_push(H, I, v.x, cb);     thr = H[0]; }
                if (v.y < thr) { heap_push(H, I, v.y, cb + 1); thr = H[0]; }
                if (v.z < thr) { heap_push(H, I, v.z, cb + 2); thr = H[0]; }
                if (v.w < thr) { heap_push(H, I, v.w, cb + 3); thr = H[0]; }
            }
        }
        __syncthreads();
    }

    // emit candidate indices
    if (tid < 128) {
        int row = qb * 128 + tid;
        int* dst = cand + (size_t)row * (NSPLIT * K2N) + s * K2N;
#pragma unroll
        for (int j = 0; j < K2N; ++j) dst[j] = hi[tid * 65 + j];
    }
}

// ---------------- phase 2: exact fp32 rescore + top-50 + output ----------------
__global__ void __launch_bounds__(256)
p2_kernel(const float* __restrict__ q, const float* __restrict__ q2g,
          const float* __restrict__ k2g, const float* __restrict__ keys,
          const float* __restrict__ vals, const float* __restrict__ net,
          const int* __restrict__ cand, float* __restrict__ out) {
    __shared__ float qs[128];
    __shared__ float ds[256];
    __shared__ int isx[256];
    __shared__ float part[4];
    const int row = blockIdx.x;
    const int tid = threadIdx.x;
    if (tid < 128) qs[tid] = q[(size_t)row * ND + tid];
    __syncthreads();

    int c = cand[(size_t)row * (NSPLIT * K2N) + tid];
    const float4* kr = (const float4*)(keys + (size_t)c * ND);
    float dot = 0.f;
#pragma unroll 8
    for (int i = 0; i < 32; ++i) {
        float4 k4 = kr[i];
        float4 q4 = *(const float4*)(qs + i * 4);
        dot = fmaf(k4.x, q4.x, dot);
        dot = fmaf(k4.y, q4.y, dot);
        dot = fmaf(k4.z, q4.z, dot);
        dot = fmaf(k4.w, q4.w, dot);
    }
    ds[tid] = q2g[row] + k2g[c] - 2.f * dot;
    isx[tid] = c;
    __syncthreads();

    // bitonic sort 256 by (dist, idx) ascending
    for (int k = 2; k <= 256; k <<= 1) {
        for (int j = k >> 1; j > 0; j >>= 1) {
            int p = tid ^ j;
            if (p > tid) {
                float d1 = ds[tid], d2 = ds[p];
                int i1 = isx[tid], i2 = isx[p];
                bool up = (tid & k) == 0;
                bool gt = (d1 > d2) || (d1 == d2 && i1 > i2);
                if (up ? gt : !gt) {
                    ds[tid] = d2; ds[p] = d1;
                    isx[tid] = i2; isx[p] = i1;
                }
            }
            __syncthreads();
        }
    }

    float wgt = 0.f, wv = 0.f;
    if (tid < NK) {
        wgt = 1.f / (ds[tid] + 1e-7f);
        wv = wgt * vals[isx[tid]];
    }
    if (tid < 64) {
        float ws = warp_allred(wgt), vs = warp_allred(wv);
        if ((tid & 31) == 0) { part[tid >> 5] = ws; part[2 + (tid >> 5)] = vs; }
    }
    __syncthreads();
    if (tid == 0) {
        float W = part[0] + part[1], V = part[2] + part[3];
        out[row] = 0.9f * (V / W) + 0.1f * net[row];
    }
}

// ---------------- launch ----------------
extern "C" void kernel_launch(void* const* d_in, const int* in_sizes, int n_in,
                              void* d_out, int out_size) {
    const float* states     = (const float*)d_in[0];
    const float* W1         = (const float*)d_in[1];
    const float* b1         = (const float*)d_in[2];
    const float* W2         = (const float*)d_in[3];
    const float* b2         = (const float*)d_in[4];
    const float* ln_g       = (const float*)d_in[5];
    const float* ln_b       = (const float*)d_in[6];
    const float* mem_keys   = (const float*)d_in[7];
    const float* mem_values = (const float*)d_in[8];
    const float* V1         = (const float*)d_in[9];
    const float* c1         = (const float*)d_in[10];
    const float* V2         = (const float*)d_in[11];
    const float* c2         = (const float*)d_in[12];
    const float* V3         = (const float*)d_in[13];
    const float* c3         = (const float*)d_in[14];
    float* out = (float*)d_out;

    void *ph, *pqpre, *pq, *pq2, *pk2, *pv1, *pv2, *pnet, *pk16, *pcand;
    cudaGetSymbolAddress(&ph, g_h);
    cudaGetSymbolAddress(&pqpre, g_qpre);
    cudaGetSymbolAddress(&pq, g_q);
    cudaGetSymbolAddress(&pq2, g_q2);
    cudaGetSymbolAddress(&pk2, g_k2);
    cudaGetSymbolAddress(&pv1, g_v1);
    cudaGetSymbolAddress(&pv2, g_v2);
    cudaGetSymbolAddress(&pnet, g_net);
    cudaGetSymbolAddress(&pk16, g_keys16);
    cudaGetSymbolAddress(&pcand, g_cand);

    cudaFuncSetAttribute(p1_kernel, cudaFuncAttributeMaxDynamicSharedMemorySize, SM_TOT);

    cvt_keys_kernel<<<(NM * ND / 4) / 256, 256>>>(mem_keys, (__nv_bfloat16*)pk16);
    k2_kernel<<<NM / 8, 256>>>(mem_keys, (float*)pk2);

    gemm_kernel<1><<<dim3(NH / 64, NB / 64), 256>>>(states, W1, b1, (float*)ph, NB, NH, NS);
    gemm_kernel<1><<<dim3(NH / 64, NB / 64), 256>>>(states, V1, c1, (float*)pv1, NB, NH, NS);
    gemm_kernel<0><<<dim3(ND / 64, NB / 64), 256>>>((const float*)ph, W2, b2, (float*)pqpre, NB, ND, NH);
    gemm_kernel<1><<<dim3(ND / 64, NB / 64), 256>>>((const float*)pv1, V2, c2, (float*)pv2, NB, ND, NH);

    ln_kernel<<<NB / 8, 256>>>((const float*)pqpre, ln_g, ln_b, (float*)pq, (float*)pq2);
    net_kernel<<<NB / 8, 256>>>((const float*)pv2, V3, c3, (float*)pnet);

    p1_kernel<<<dim3(NSPLIT, NB / 128), 256, SM_TOT>>>((const float*)pq,
                                                       (const __nv_bfloat16*)pk16,
                                                       (const float*)pk2, (int*)pcand);

    p2_kernel<<<NB, 256>>>((const float*)pq, (const float*)pq2, (const float*)pk2,
                           mem_keys, mem_values, (const float*)pnet,
                           (const int*)pcand, out);
}

// round 5
// speedup vs baseline: 1.8458x; 1.0068x over previous
#include <cuda_runtime.h>
#include <cuda_bf16.h>
#include <cstdint>
#include <cstddef>

#define NB 4096
#define NS 544
#define NH 256
#define ND 128
#define NM 50000
#define NK 50
#define K2N 64           // candidates kept per split
#define NSPLIT 4
#define SPLEN 12544      // 98 * 128
#define TILEN 128
#define F_INF __int_as_float(0x7f800000)

// ---------------- scratch (static device globals; no allocations) ----------
__device__ float g_h[NB * NH];
__device__ float g_qpre[NB * ND];
__device__ float g_q[NB * ND];
__device__ float g_q2[NB];
__device__ float g_k2[NM];
__device__ float g_v1[NB * NH];
__device__ float g_v2[NB * ND];
__device__ float g_net[NB];
__device__ __nv_bfloat16 g_keys16[NM * ND];
__device__ int g_cand[NB * (NSPLIT * K2N)];

// ---------------- helpers ----------------
__device__ __forceinline__ uint32_t smem_u32(const void* p) {
    uint32_t a;
    asm("{ .reg .u64 t; cvta.to.shared.u64 t, %1; cvt.u32.u64 %0, t; }" : "=r"(a) : "l"(p));
    return a;
}
__device__ __forceinline__ void cp16(uint32_t dst, const void* src) {
    asm volatile("cp.async.ca.shared.global [%0], [%1], 16;\n" :: "r"(dst), "l"(src));
}
__device__ __forceinline__ float warp_allred(float v) {
#pragma unroll
    for (int o = 16; o; o >>= 1) v += __shfl_xor_sync(0xffffffffu, v, o);
    return v;
}
__device__ __forceinline__ void ldsm_x4(uint32_t& r0, uint32_t& r1, uint32_t& r2,
                                        uint32_t& r3, uint32_t addr) {
    asm volatile("ldmatrix.sync.aligned.m8n8.x4.shared.b16 {%0,%1,%2,%3}, [%4];"
                 : "=r"(r0), "=r"(r1), "=r"(r2), "=r"(r3) : "r"(addr));
}
__device__ __forceinline__ void mma_bf16(float* c, const uint32_t* a, uint32_t b0, uint32_t b1) {
    asm volatile("mma.sync.aligned.m16n8k16.row.col.f32.bf16.bf16.f32 "
                 "{%0,%1,%2,%3}, {%4,%5,%6,%7}, {%8,%9}, {%0,%1,%2,%3};"
                 : "+f"(c[0]), "+f"(c[1]), "+f"(c[2]), "+f"(c[3])
                 : "r"(a[0]), "r"(a[1]), "r"(a[2]), "r"(a[3]), "r"(b0), "r"(b1));
}

// ---------------- k2 / key conversion ----------------
__global__ void k2_kernel(const float* __restrict__ keys, float* __restrict__ k2) {
    int w = (blockIdx.x * blockDim.x + threadIdx.x) >> 5;
    int lane = threadIdx.x & 31;
    float4 v = *(const float4*)(keys + (size_t)w * ND + lane * 4);
    float s = v.x * v.x + v.y * v.y + v.z * v.z + v.w * v.w;
    s = warp_allred(s);
    if (lane == 0) k2[w] = s;
}

__global__ void cvt_keys_kernel(const float* __restrict__ keys, __nv_bfloat16* __restrict__ out) {
    int i = blockIdx.x * blockDim.x + threadIdx.x;
    float4 v = *(const float4*)(keys + (size_t)i * 4);
    __nv_bfloat162 a = __floats2bfloat162_rn(v.x, v.y);
    __nv_bfloat162 b = __floats2bfloat162_rn(v.z, v.w);
    uint2 o;
    o.x = *(uint32_t*)&a;
    o.y = *(uint32_t*)&b;
    *(uint2*)(out + (size_t)i * 4) = o;
}

// ---------------- encoder GEMMs (SIMT, small) ----------------
template <int RELU>
__global__ void gemm_kernel(const float* __restrict__ A, const float* __restrict__ W,
                            const float* __restrict__ bias, float* __restrict__ C,
                            int Md, int Nd, int Kd) {
    __shared__ float As[64][17];
    __shared__ float Bs[16][64];
    const int tid = threadIdx.x;
    const int tn = tid & 15, tm = tid >> 4;
    const int row0 = blockIdx.y << 6, col0 = blockIdx.x << 6;
    const int arow = tid >> 2, acol = (tid & 3) << 2;
    const int brow = tid >> 4, bcol = (tid & 15) << 2;
    float acc[4][4] = {};
    for (int k0 = 0; k0 < Kd; k0 += 16) {
        float4 av = *(const float4*)(A + (size_t)(row0 + arow) * Kd + k0 + acol);
        float4 bv = *(const float4*)(W + (size_t)(k0 + brow) * Nd + col0 + bcol);
        As[arow][acol + 0] = av.x; As[arow][acol + 1] = av.y;
        As[arow][acol + 2] = av.z; As[arow][acol + 3] = av.w;
        *(float4*)&Bs[brow][bcol] = bv;
        __syncthreads();
#pragma unroll
        for (int kk = 0; kk < 16; ++kk) {
            float aa[4];
#pragma unroll
            for (int i = 0; i < 4; ++i) aa[i] = As[tm * 4 + i][kk];
            float4 b4 = *(float4*)&Bs[kk][tn * 4];
            float bb[4] = {b4.x, b4.y, b4.z, b4.w};
#pragma unroll
            for (int i = 0; i < 4; ++i)
#pragma unroll
                for (int j = 0; j < 4; ++j)
                    acc[i][j] = fmaf(aa[i], bb[j], acc[i][j]);
        }
        __syncthreads();
    }
    float4 bz = *(const float4*)(bias + col0 + tn * 4);
    float bb[4] = {bz.x, bz.y, bz.z, bz.w};
#pragma unroll
    for (int i = 0; i < 4; ++i) {
        float v0 = acc[i][0] + bb[0], v1 = acc[i][1] + bb[1];
        float v2 = acc[i][2] + bb[2], v3 = acc[i][3] + bb[3];
        if (RELU) {
            v0 = fmaxf(v0, 0.f); v1 = fmaxf(v1, 0.f);
            v2 = fmaxf(v2, 0.f); v3 = fmaxf(v3, 0.f);
        }
        float4 o; o.x = v0; o.y = v1; o.z = v2; o.w = v3;
        *(float4*)(C + (size_t)(row0 + tm * 4 + i) * Nd + col0 + tn * 4) = o;
    }
}

__global__ void ln_kernel(const float* __restrict__ x, const float* __restrict__ g,
                          const float* __restrict__ b, float* __restrict__ q,
                          float* __restrict__ q2) {
    int row = (blockIdx.x * blockDim.x + threadIdx.x) >> 5;
    int lane = threadIdx.x & 31;
    float4 v = *(const float4*)(x + (size_t)row * ND + lane * 4);
    float mu = warp_allred(v.x + v.y + v.z + v.w) * (1.f / 128.f);
    float d0 = v.x - mu, d1 = v.y - mu, d2 = v.z - mu, d3 = v.w - mu;
    float var = warp_allred(d0 * d0 + d1 * d1 + d2 * d2 + d3 * d3) * (1.f / 128.f);
    float inv = rsqrtf(var + 1e-5f);
    float4 gg = *(const float4*)(g + lane * 4);
    float4 bb = *(const float4*)(b + lane * 4);
    float4 o;
    o.x = d0 * inv * gg.x + bb.x;
    o.y = d1 * inv * gg.y + bb.y;
    o.z = d2 * inv * gg.z + bb.z;
    o.w = d3 * inv * gg.w + bb.w;
    *(float4*)(q + (size_t)row * ND + lane * 4) = o;
    float qq = warp_allred(o.x * o.x + o.y * o.y + o.z * o.z + o.w * o.w);
    if (lane == 0) q2[row] = qq;
}

__global__ void net_kernel(const float* __restrict__ v2, const float* __restrict__ V3,
                           const float* __restrict__ c3, float* __restrict__ net) {
    int row = (blockIdx.x * blockDim.x + threadIdx.x) >> 5;
    int lane = threadIdx.x & 31;
    float4 a = *(const float4*)(v2 + (size_t)row * ND + lane * 4);
    float4 w = *(const float4*)(V3 + lane * 4);
    float s = warp_allred(a.x * w.x + a.y * w.y + a.z * w.z + a.w * w.w);
    if (lane == 0) net[row] = s + c3[0];
}

// ---------------- phase 1: mma.sync bf16 GEMM + streaming top-64 ----------------
// 512 threads / 16 warps; warp w: q rows ((w&7)*16..+16) x keys ((w>>3)*64..+64)
// smem byte offsets:
#define SM_B    0                 // 2 x 32768: key tiles, swizzled (row*256 + (u^(row&7))*16)
#define SM_DIST 65536             // 128 x 132 floats = 67584  (also q bf16 staging at start)
#define SM_HD   133120            // 128 x 65 floats (heap dists, stride 65)
#define SM_HI   166400            // 128 x 65 ints
#define SM_K2   199680            // 2 x 128 floats
#define SM_TOT  200704

__device__ __forceinline__ void heap_push(float* H, int* I, float sc, int gm) {
    int p = 0;
    while (true) {
        int l = 2 * p + 1;
        if (l >= K2N) break;
        int rc = l + 1;
        float dl = H[l];
        float dr = (rc < K2N) ? H[rc] : -1e30f;
        int big; float db;
        if (dr > dl) { big = rc; db = dr; } else { big = l; db = dl; }
        if (db > sc) { H[p] = db; I[p] = I[big]; p = big; } else break;
    }
    H[p] = sc; I[p] = gm;
}

__device__ __forceinline__ void p1_load_tile(int t, int m0s, int tid, uint32_t sb,
                                             float* k2s, const __nv_bfloat16* keys16,
                                             const float* k2g) {
    const int buf = t & 1;
    const int m0t = m0s + t * TILEN;
#pragma unroll
    for (int it = 0; it < 4; ++it) {
        int idx = tid + (it << 9);
        int row = idx >> 4, u = idx & 15;
        int gm = m0t + row;
        if (gm < NM)
            cp16(sb + SM_B + buf * 32768 + row * 256 + ((u ^ (row & 7)) << 4),
                 keys16 + (size_t)gm * ND + u * 8);
    }
    if (tid < 32) {
        int g0 = m0t + tid * 4;
        if (g0 + 3 < NM) {
            cp16(sb + SM_K2 + buf * 512 + (tid << 4), k2g + g0);
        } else {
#pragma unroll
            for (int u2 = 0; u2 < 4; ++u2) {
                int g = g0 + u2;
                k2s[buf * 128 + tid * 4 + u2] = (g < NM) ? __ldg(k2g + g) : F_INF;
            }
        }
    }
    asm volatile("cp.async.commit_group;\n" ::: "memory");
}

__global__ void __launch_bounds__(512, 1)
p1_kernel(const float* __restrict__ q, const __nv_bfloat16* __restrict__ keys16,
          const float* __restrict__ k2g, int* __restrict__ cand) {
    extern __shared__ __align__(16) char sm[];
    const uint32_t sb = smem_u32(sm);
    float* dist = (float*)(sm + SM_DIST);
    float* hd = (float*)(sm + SM_HD);
    int* hi = (int*)(sm + SM_HI);
    float* k2s = (float*)(sm + SM_K2);

    const int tid = threadIdx.x;
    const int w = tid >> 5;
    const int lt = tid & 31;
    const int wr = w & 7;          // q-row group
    const int wh = w >> 3;         // key half (0/1)
    const int s = blockIdx.x, qb = blockIdx.y;
    const int m0s = s * SPLEN;
    const int mlen = min(SPLEN, NM - m0s);
    const int T = (mlen + TILEN - 1) / TILEN;

    // init heaps (128 rows x 64, stride 65)
    for (int i = tid; i < 128 * K2N; i += 512) {
        int r = i >> 6, j = i & 63;
        hd[r * 65 + j] = F_INF;
        hi[r * 65 + j] = m0s;
    }

    // stage q block as bf16 (swizzled) into the DIST region
#pragma unroll
    for (int it = 0; it < 4; ++it) {
        int idx = tid + (it << 9);
        int row = idx >> 4, u = idx & 15;
        const float* src = q + (size_t)(qb * 128 + row) * ND + u * 8;
        float4 v0 = *(const float4*)src;
        float4 v1 = *(const float4*)(src + 4);
        __nv_bfloat162 p0 = __floats2bfloat162_rn(v0.x, v0.y);
        __nv_bfloat162 p1 = __floats2bfloat162_rn(v0.z, v0.w);
        __nv_bfloat162 p2 = __floats2bfloat162_rn(v1.x, v1.y);
        __nv_bfloat162 p3 = __floats2bfloat162_rn(v1.z, v1.w);
        uint4 pk;
        pk.x = *(uint32_t*)&p0; pk.y = *(uint32_t*)&p1;
        pk.z = *(uint32_t*)&p2; pk.w = *(uint32_t*)&p3;
        *(uint4*)(sm + SM_DIST + row * 256 + ((u ^ (row & 7)) << 4)) = pk;
    }
    __syncthreads();

    // load persistent A fragments (warp covers q rows [wr*16, wr*16+16))
    uint32_t af[8][4];
    {
        int mrow = wr * 16 + (lt & 7) + ((lt >> 3) & 1) * 8;
        int kh = lt >> 4;
        uint32_t abase = sb + SM_DIST + mrow * 256;
        int msw = mrow & 7;
#pragma unroll
        for (int kk = 0; kk < 8; ++kk)
            ldsm_x4(af[kk][0], af[kk][1], af[kk][2], af[kk][3],
                    abase + ((((kk << 1) | kh) ^ msw) << 4));
    }
    __syncthreads();   // staging region now free -> dist buffer

    p1_load_tile(0, m0s, tid, sb, k2s, keys16, k2g);

    float thr = F_INF;
    float* H = hd + tid * 65;
    int* I = hi + tid * 65;
    const int nbase = (lt >> 4) * 8 + (lt & 7);   // n within 16-key pair for ldmatrix B
    const int hh = (lt >> 3) & 1;
    const int r0 = wr * 16 + (lt >> 2);
    const int cbase = (lt & 3) << 1;

    for (int t = 0; t < T; ++t) {
        const int buf = t & 1;
        asm volatile("cp.async.wait_group 0;\n" ::: "memory");
        __syncthreads();
        if (t + 1 < T) p1_load_tile(t + 1, m0s, tid, sb, k2s, keys16, k2g);

        // MMA: 16 q rows x 64 keys x 128 dims per warp
        float acc[8][4];
#pragma unroll
        for (int j = 0; j < 8; ++j)
#pragma unroll
            for (int e = 0; e < 4; ++e) acc[j][e] = 0.f;

        const uint32_t bbase = sb + SM_B + buf * 32768 + wh * 16384;  // 64 keys * 256B
#pragma unroll
        for (int kk = 0; kk < 8; ++kk) {
#pragma unroll
            for (int jp = 0; jp < 4; ++jp) {
                int n = jp * 16 + nbase;
                uint32_t addr = bbase + n * 256 + ((((kk << 1) | hh) ^ (n & 7)) << 4);
                uint32_t b0, b1, b2, b3;
                ldsm_x4(b0, b1, b2, b3, addr);
                mma_bf16(acc[2 * jp], af[kk], b0, b1);
                mma_bf16(acc[2 * jp + 1], af[kk], b2, b3);
            }
        }

        // write scores (k2 - 2*dot) to dist[128][132]
#pragma unroll
        for (int j = 0; j < 8; ++j) {
            int c = wh * 64 + j * 8 + cbase;
            float2 kk2 = *(float2*)(k2s + buf * 128 + c);
            float2 s0, s1;
            s0.x = fmaf(acc[j][0], -2.f, kk2.x);
            s0.y = fmaf(acc[j][1], -2.f, kk2.y);
            s1.x = fmaf(acc[j][2], -2.f, kk2.x);
            s1.y = fmaf(acc[j][3], -2.f, kk2.y);
            *(float2*)(dist + r0 * 132 + c) = s0;
            *(float2*)(dist + (r0 + 8) * 132 + c) = s1;
        }
        __syncthreads();

        // per-row scan + heap maintenance (thread tid owns q row tid)
        if (tid < 128) {
            const int m0t = m0s + t * TILEN;
            const float* drow = dist + tid * 132;
#pragma unroll 8
            for (int c4 = 0; c4 < 32; ++c4) {
                float4 v = *(const float4*)(drow + c4 * 4);
                int cb = m0t + c4 * 4;
                if (v.x < thr) { heap_push(H, I, v.x, cb);     thr = H[0]; }
                if (v.y < thr) { heap_push(H, I, v.y, cb + 1); thr = H[0]; }
                if (v.z < thr) { heap_push(H, I, v.z, cb + 2); thr = H[0]; }
                if (v.w < thr) { heap_push(H, I, v.w, cb + 3); thr = H[0]; }
            }
        }
        __syncthreads();
    }

    // emit candidate indices
    if (tid < 128) {
        int row = qb * 128 + tid;
        int* dst = cand + (size_t)row * (NSPLIT * K2N) + s * K2N;
#pragma unroll
        for (int j = 0; j < K2N; ++j) dst[j] = hi[tid * 65 + j];
    }
}

// ---------------- phase 2: exact fp32 rescore + top-50 + output ----------------
__global__ void __launch_bounds__(256)
p2_kernel(const float* __restrict__ q, const float* __restrict__ q2g,
          const float* __restrict__ k2g, const float* __restrict__ keys,
          const float* __restrict__ vals, const float* __restrict__ net,
          const int* __restrict__ cand, float* __restrict__ out) {
    __shared__ float qs[128];
    __shared__ float ds[256];
    __shared__ int isx[256];
    __shared__ float part[4];
    const int row = blockIdx.x;
    const int tid = threadIdx.x;
    if (tid < 128) qs[tid] = q[(size_t)row * ND + tid];
    __syncthreads();

    int c = cand[(size_t)row * (NSPLIT * K2N) + tid];
    const float4* kr = (const float4*)(keys + (size_t)c * ND);
    float dot = 0.f;
#pragma unroll 8
    for (int i = 0; i < 32; ++i) {
        float4 k4 = kr[i];
        float4 q4 = *(const float4*)(qs + i * 4);
        dot = fmaf(k4.x, q4.x, dot);
        dot = fmaf(k4.y, q4.y, dot);
        dot = fmaf(k4.z, q4.z, dot);
        dot = fmaf(k4.w, q4.w, dot);
    }
    ds[tid] = q2g[row] + k2g[c] - 2.f * dot;
    isx[tid] = c;
    __syncthreads();

    // bitonic sort 256 by (dist, idx) ascending
    for (int k = 2; k <= 256; k <<= 1) {
        for (int j = k >> 1; j > 0; j >>= 1) {
            int p = tid ^ j;
            if (p > tid) {
                float d1 = ds[tid], d2 = ds[p];
                int i1 = isx[tid], i2 = isx[p];
                bool up = (tid & k) == 0;
                bool gt = (d1 > d2) || (d1 == d2 && i1 > i2);
                if (up ? gt : !gt) {
                    ds[tid] = d2; ds[p] = d1;
                    isx[tid] = i2; isx[p] = i1;
                }
            }
            __syncthreads();
        }
    }

    float wgt = 0.f, wv = 0.f;
    if (tid < NK) {
        wgt = 1.f / (ds[tid] + 1e-7f);
        wv = wgt * vals[isx[tid]];
    }
    if (tid < 64) {
        float ws = warp_allred(wgt), vs = warp_allred(wv);
        if ((tid & 31) == 0) { part[tid >> 5] = ws; part[2 + (tid >> 5)] = vs; }
    }
    __syncthreads();
    if (tid == 0) {
        float W = part[0] + part[1], V = part[2] + part[3];
        out[row] = 0.9f * (V / W) + 0.1f * net[row];
    }
}

// ---------------- launch ----------------
extern "C" void kernel_launch(void* const* d_in, const int* in_sizes, int n_in,
                              void* d_out, int out_size) {
    const float* states     = (const float*)d_in[0];
    const float* W1         = (const float*)d_in[1];
    const float* b1         = (const float*)d_in[2];
    const float* W2         = (const float*)d_in[3];
    const float* b2         = (const float*)d_in[4];
    const float* ln_g       = (const float*)d_in[5];
    const float* ln_b       = (const float*)d_in[6];
    const float* mem_keys   = (const float*)d_in[7];
    const float* mem_values = (const float*)d_in[8];
    const float* V1         = (const float*)d_in[9];
    const float* c1         = (const float*)d_in[10];
    const float* V2         = (const float*)d_in[11];
    const float* c2         = (const float*)d_in[12];
    const float* V3         = (const float*)d_in[13];
    const float* c3         = (const float*)d_in[14];
    float* out = (float*)d_out;

    void *ph, *pqpre, *pq, *pq2, *pk2, *pv1, *pv2, *pnet, *pk16, *pcand;
    cudaGetSymbolAddress(&ph, g_h);
    cudaGetSymbolAddress(&pqpre, g_qpre);
    cudaGetSymbolAddress(&pq, g_q);
    cudaGetSymbolAddress(&pq2, g_q2);
    cudaGetSymbolAddress(&pk2, g_k2);
    cudaGetSymbolAddress(&pv1, g_v1);
    cudaGetSymbolAddress(&pv2, g_v2);
    cudaGetSymbolAddress(&pnet, g_net);
    cudaGetSymbolAddress(&pk16, g_keys16);
    cudaGetSymbolAddress(&pcand, g_cand);

    cudaFuncSetAttribute(p1_kernel, cudaFuncAttributeMaxDynamicSharedMemorySize, SM_TOT);

    // ---- launches ordered so p1 is launch #6 (ncu -s 5 -c 1 profiles it) ----
    cvt_keys_kernel<<<(NM * ND / 4) / 256, 256>>>(mem_keys, (__nv_bfloat16*)pk16);      // 1
    k2_kernel<<<NM / 8, 256>>>(mem_keys, (float*)pk2);                                   // 2
    gemm_kernel<1><<<dim3(NH / 64, NB / 64), 256>>>(states, W1, b1, (float*)ph, NB, NH, NS);          // 3
    gemm_kernel<0><<<dim3(ND / 64, NB / 64), 256>>>((const float*)ph, W2, b2, (float*)pqpre, NB, ND, NH); // 4
    ln_kernel<<<NB / 8, 256>>>((const float*)pqpre, ln_g, ln_b, (float*)pq, (float*)pq2);             // 5

    p1_kernel<<<dim3(NSPLIT, NB / 128), 512, SM_TOT>>>((const float*)pq,                 // 6 <- profiled
                                                       (const __nv_bfloat16*)pk16,
                                                       (const float*)pk2, (int*)pcand);

    gemm_kernel<1><<<dim3(NH / 64, NB / 64), 256>>>(states, V1, c1, (float*)pv1, NB, NH, NS);         // 7
    gemm_kernel<1><<<dim3(ND / 64, NB / 64), 256>>>((const float*)pv1, V2, c2, (float*)pv2, NB, ND, NH); // 8
    net_kernel<<<NB / 8, 256>>>((const float*)pv2, V3, c3, (float*)pnet);                // 9

    p2_kernel<<<NB, 256>>>((const float*)pq, (const float*)pq2, (const float*)pk2,
                           mem_keys, mem_values, (const float*)pnet,
                           (const int*)pcand, out);                                      // 10
}